// round 3
// baseline (speedup 1.0000x reference)
#include <cuda_runtime.h>
#include <math.h>

#define Hs   64
#define SEQ  2048
#define Bt   256
#define IN   32

typedef unsigned long long u64;

__device__ __forceinline__ u64 fma2(u64 a, u64 b, u64 c) {
    u64 d;
    asm("fma.rn.f32x2 %0, %1, %2, %3;" : "=l"(d) : "l"(a), "l"(b), "l"(c));
    return d;
}
__device__ __forceinline__ u64 pk(float a, float b) {
    u64 r;
    asm("mov.b64 %0, {%1, %2};" : "=l"(r) : "f"(a), "f"(b));
    return r;
}
__device__ __forceinline__ float hsum(u64 v) {
    float a, b;
    asm("mov.b64 {%0, %1}, %2;" : "=f"(a), "=f"(b) : "l"(v));
    return a + b;
}
__device__ __forceinline__ float ex2a(float x) {
    float y; asm("ex2.approx.f32 %0, %1;" : "=f"(y) : "f"(x)); return y;
}
__device__ __forceinline__ float rcpa(float x) {
    float y; asm("rcp.approx.f32 %0, %1;" : "=f"(y) : "f"(x)); return y;
}
__device__ __forceinline__ float sigf(float x) {
    return rcpa(1.0f + ex2a(-1.4426950408889634f * x));
}
__device__ __forceinline__ float tanhfa(float x) {
    return fmaf(2.0f, sigf(2.0f * x), -1.0f);
}

// smem floats:
//  [0,16384)        Whh1 [k4=16][gj=256] as 16B units (64KB)
//  +64    Wh
//  +512   sG0 [2][256] activated gates L0
//  +512   sG1 [2][256] activated gates L1
//  +128   sH0 [2][64]
//  +128   sH1 [2][64]
//  +128   sX  [2][2][32]
//  +4     sPr
#define SMEM_FLOATS (16384 + 64 + 512 + 512 + 128 + 128 + 128 + 4)

__global__ void __launch_bounds__(512, 1)
lstm2_pipe(const float* __restrict__ x,
           const float* __restrict__ h0g,
           const float* __restrict__ c0g,
           const float* __restrict__ Wih0,
           const float* __restrict__ Whh0,
           const float* __restrict__ bih0,
           const float* __restrict__ bhh0,
           const float* __restrict__ Wih1,
           const float* __restrict__ Whh1,
           const float* __restrict__ bih1,
           const float* __restrict__ bhh1,
           const float* __restrict__ Wh,
           const float* __restrict__ bhp,
           float* __restrict__ out)
{
    extern __shared__ float sm[];
    float* sW1h = sm;
    float* sWh  = sm + 16384;
    float* sG0  = sWh + 64;
    float* sG1  = sG0 + 512;
    float* sH0  = sG1 + 512;
    float* sH1  = sH0 + 128;
    float* sX   = sH1 + 128;
    float* sPr  = sX + 128;

    const int tid = threadIdx.x;
    const int r0  = blockIdx.x * 2;
    const bool isA = tid < 256;          // A: layer-0 gate threads
    const int g   = tid & 255;           // gate row
    const int gsel = g >> 6;             // 0:i 1:f 2:g 3:o

    // ---- per-thread register weights
    u64 wx0[IN / 2];   // A only
    u64 wh0[Hs / 2];   // A only
    u64 wx1[Hs / 2];   // B only
    float bias;
    if (isA) {
        const u64* p0 = (const u64*)(Wih0 + g * IN);
        const u64* p1 = (const u64*)(Whh0 + g * Hs);
#pragma unroll
        for (int k = 0; k < IN / 2; k++) wx0[k] = p0[k];
#pragma unroll
        for (int k = 0; k < Hs / 2; k++) wh0[k] = p1[k];
        bias = bih0[g] + bhh0[g];
    } else {
        const u64* p2 = (const u64*)(Wih1 + g * Hs);
#pragma unroll
        for (int k = 0; k < Hs / 2; k++) wx1[k] = p2[k];
        bias = bih1[g] + bhh1[g];
    }
    const u64 bp = pk(bias, 0.0f);

    // ---- smem init (all 512 threads)
    for (int idx = tid; idx < 16 * 256; idx += 512) {
        int gj = idx & 255, k4 = idx >> 8;
        ((float4*)sW1h)[idx] = *(const float4*)(Whh1 + gj * Hs + k4 * 4);
    }
    if (tid < 64) sWh[tid] = Wh[tid];

    float c0r = 0.0f, c1r = 0.0f;
    if (tid < 128) {                               // A updaters: layer0 state
        int r = tid >> 6, j = tid & 63;
        sH0[r * 64 + j] = h0g[(size_t)(r0 + r) * Hs + j];
        c0r = c0g[(size_t)(r0 + r) * Hs + j];
    }
    if (tid >= 256 && tid < 384) {                 // B updaters: layer1 state
        int ub = tid - 256, r = ub >> 6, j = ub & 63;
        sH1[r * 64 + j] = h0g[(size_t)Bt * Hs + (size_t)(r0 + r) * Hs + j];
        c1r = c0g[(size_t)Bt * Hs + (size_t)(r0 + r) * Hs + j];
    }
    if (tid < 16) {
        int row = tid >> 3, q = tid & 7;
        ((float4*)sX)[row * 8 + q] =
            *(const float4*)(x + (size_t)(r0 + row) * SEQ * IN + q * 4);
    }
    __syncthreads();

    const float bh0 = bhp[0];

    // pipeline: iteration u — A computes L0(t=u), B computes L1(t=u-1)
    for (int u = 0; u <= SEQ; u++) {
        float4 xf = make_float4(0.f, 0.f, 0.f, 0.f);

        // ================= phase 1: gates =================
        if (isA) {
            if (tid < 16 && u + 1 < SEQ) {         // prefetch x(u+1)
                int row = tid >> 3, q = tid & 7;
                xf = *(const float4*)(x + (size_t)(r0 + row) * SEQ * IN
                                        + (size_t)(u + 1) * IN + q * 4);
            }
            if (u < SEQ) {
                const ulonglong2* xr0 = (const ulonglong2*)(sX + (u & 1) * 64);
                const ulonglong2* xr1 = (const ulonglong2*)(sX + (u & 1) * 64 + 32);
                const ulonglong2* h0a = (const ulonglong2*)sH0;
                const ulonglong2* h0b = (const ulonglong2*)(sH0 + 64);
                u64 a0 = bp, a1 = bp;
#pragma unroll
                for (int k = 0; k < 8; k++) {
                    ulonglong2 v0 = xr0[k], v1 = xr1[k];
                    a0 = fma2(wx0[2*k],   v0.x, a0);
                    a0 = fma2(wx0[2*k+1], v0.y, a0);
                    a1 = fma2(wx0[2*k],   v1.x, a1);
                    a1 = fma2(wx0[2*k+1], v1.y, a1);
                }
#pragma unroll
                for (int k = 0; k < 16; k++) {
                    ulonglong2 v0 = h0a[k], v1 = h0b[k];
                    a0 = fma2(wh0[2*k],   v0.x, a0);
                    a0 = fma2(wh0[2*k+1], v0.y, a0);
                    a1 = fma2(wh0[2*k],   v1.x, a1);
                    a1 = fma2(wh0[2*k+1], v1.y, a1);
                }
                float g0 = hsum(a0), g1 = hsum(a1);
                sG0[g]       = (gsel == 2) ? tanhfa(g0) : sigf(g0);
                sG0[256 + g] = (gsel == 2) ? tanhfa(g1) : sigf(g1);
            }
        } else {
            if (u >= 1) {
                const ulonglong2* h0a = (const ulonglong2*)sH0;   // h0(u-1)
                const ulonglong2* h0b = (const ulonglong2*)(sH0 + 64);
                const ulonglong2* h1a = (const ulonglong2*)sH1;   // h1(u-2)
                const ulonglong2* h1b = (const ulonglong2*)(sH1 + 64);
                const ulonglong2* wp  = (const ulonglong2*)sW1h;
                u64 a0 = bp, a1 = bp;
#pragma unroll
                for (int k = 0; k < 16; k++) {
                    ulonglong2 v0 = h0a[k], v1 = h0b[k];
                    a0 = fma2(wx1[2*k],   v0.x, a0);
                    a0 = fma2(wx1[2*k+1], v0.y, a0);
                    a1 = fma2(wx1[2*k],   v1.x, a1);
                    a1 = fma2(wx1[2*k+1], v1.y, a1);
                }
#pragma unroll
                for (int k4 = 0; k4 < 16; k4++) {
                    ulonglong2 w  = wp[k4 * 256 + g];
                    ulonglong2 v0 = h1a[k4], v1 = h1b[k4];
                    a0 = fma2(w.x, v0.x, a0);
                    a0 = fma2(w.y, v0.y, a0);
                    a1 = fma2(w.x, v1.x, a1);
                    a1 = fma2(w.y, v1.y, a1);
                }
                float g0 = hsum(a0), g1 = hsum(a1);
                sG1[g]       = (gsel == 2) ? tanhfa(g0) : sigf(g0);
                sG1[256 + g] = (gsel == 2) ? tanhfa(g1) : sigf(g1);
            }
            // head output for time u-2 (partials written in phase 2 of u-1)
            if (u >= 2 && (tid == 384 || tid == 385)) {
                int k = tid - 384;
                float v = sPr[k * 2] + sPr[k * 2 + 1] + bh0;
                out[(size_t)(r0 + k) * SEQ + (u - 2)] = sigf(v);
            }
        }
        __syncthreads();

        // ================= phase 2: updates =================
        if (tid < 128 && u < SEQ) {                // layer 0: c0, h0(u)
            int r = tid >> 6, j = tid & 63;
            float ig = sG0[r * 256 + j];
            float fg = sG0[r * 256 + 64 + j];
            float gg = sG0[r * 256 + 128 + j];
            float og = sG0[r * 256 + 192 + j];
            c0r = fg * c0r + ig * gg;
            sH0[r * 64 + j] = og * tanhfa(c0r);
        }
        if (tid >= 256 && tid < 384 && u >= 1) {   // layer 1: c1, h1(u-1)
            int ub = tid - 256, r = ub >> 6, j = ub & 63;
            float ig = sG1[r * 256 + j];
            float fg = sG1[r * 256 + 64 + j];
            float gg = sG1[r * 256 + 128 + j];
            float og = sG1[r * 256 + 192 + j];
            c1r = fg * c1r + ig * gg;
            float hn = og * tanhfa(c1r);
            sH1[r * 64 + j] = hn;
            float p = hn * sWh[j];
#pragma unroll
            for (int off = 16; off; off >>= 1)
                p += __shfl_down_sync(0xffffffffu, p, off);
            if ((ub & 31) == 0) sPr[ub >> 5] = p;  // warps 8..11 -> sPr[0..3]
        }
        if (tid < 16 && u + 1 < SEQ) {             // stage x(u+1)
            int row = tid >> 3, q = tid & 7;
            ((float4*)sX)[((u + 1) & 1) * 16 + row * 8 + q] = xf;
        }
        __syncthreads();
    }

    // final head output for time SEQ-1 (partials from iteration u=SEQ)
    if (tid == 384 || tid == 385) {
        int k = tid - 384;
        float v = sPr[k * 2] + sPr[k * 2 + 1] + bh0;
        out[(size_t)(r0 + k) * SEQ + (SEQ - 1)] = sigf(v);
    }

    // final h, c
    const size_t hb = (size_t)Bt * SEQ;
    const size_t cb = hb + 2 * (size_t)Bt * Hs;
    if (tid < 128) {
        int r = tid >> 6, j = tid & 63;
        out[hb + (size_t)(r0 + r) * Hs + j] = sH0[r * 64 + j];
        out[cb + (size_t)(r0 + r) * Hs + j] = c0r;
    }
    if (tid >= 256 && tid < 384) {
        int ub = tid - 256, r = ub >> 6, j = ub & 63;
        out[hb + Bt * Hs + (size_t)(r0 + r) * Hs + j] = sH1[r * 64 + j];
        out[cb + Bt * Hs + (size_t)(r0 + r) * Hs + j] = c1r;
    }
}

extern "C" void kernel_launch(void* const* d_in, const int* in_sizes, int n_in,
                              void* d_out, int out_size)
{
    const float* x    = (const float*)d_in[0];
    const float* h0   = (const float*)d_in[1];
    const float* c0   = (const float*)d_in[2];
    const float* Wih0 = (const float*)d_in[3];
    const float* Whh0 = (const float*)d_in[4];
    const float* bih0 = (const float*)d_in[5];
    const float* bhh0 = (const float*)d_in[6];
    const float* Wih1 = (const float*)d_in[7];
    const float* Whh1 = (const float*)d_in[8];
    const float* bih1 = (const float*)d_in[9];
    const float* bhh1 = (const float*)d_in[10];
    const float* Wh   = (const float*)d_in[11];
    const float* bh   = (const float*)d_in[12];
    float* out = (float*)d_out;

    const int smem_bytes = SMEM_FLOATS * (int)sizeof(float);
    cudaFuncSetAttribute(lstm2_pipe,
                         cudaFuncAttributeMaxDynamicSharedMemorySize, smem_bytes);
    lstm2_pipe<<<Bt / 2, 512, smem_bytes>>>(
        x, h0, c0, Wih0, Whh0, bih0, bhh0,
        Wih1, Whh1, bih1, bhh1, Wh, bh, out);
}

// round 4
// speedup vs baseline: 1.1909x; 1.1909x over previous
#include <cuda_runtime.h>
#include <math.h>

#define Hs    64
#define SEQ   2048
#define Bt    256
#define IN    32
#define GATES 256   // 4*H

typedef unsigned long long u64;

__device__ float g_xproj[(size_t)SEQ * Bt * GATES];   // [t][row][g], bias0 folded in

__device__ __forceinline__ u64 fma2(u64 a, u64 b, u64 c) {
    u64 d;
    asm("fma.rn.f32x2 %0, %1, %2, %3;" : "=l"(d) : "l"(a), "l"(b), "l"(c));
    return d;
}
__device__ __forceinline__ u64 pk(float a, float b) {
    u64 r;
    asm("mov.b64 %0, {%1, %2};" : "=l"(r) : "f"(a), "f"(b));
    return r;
}
__device__ __forceinline__ float hsum(u64 v) {
    float a, b;
    asm("mov.b64 {%0, %1}, %2;" : "=f"(a), "=f"(b) : "l"(v));
    return a + b;
}
__device__ __forceinline__ float ex2a(float x) {
    float y; asm("ex2.approx.f32 %0, %1;" : "=f"(y) : "f"(x)); return y;
}
__device__ __forceinline__ float rcpa(float x) {
    float y; asm("rcp.approx.f32 %0, %1;" : "=f"(y) : "f"(x)); return y;
}
__device__ __forceinline__ float sigf(float x) {
    return rcpa(1.0f + ex2a(-1.4426950408889634f * x));
}
__device__ __forceinline__ float tanhfa(float x) {
    return fmaf(2.0f, sigf(2.0f * x), -1.0f);
}

// ============================================================================
// Prepass: xproj[t][row][g] = Wih0[g]·x[row][t] + bih0[g] + bhh0[g]
// grid (SEQ/64, Bt), 256 threads; thread = gate g, 64 timesteps per block.
// ============================================================================
__global__ void __launch_bounds__(256)
xproj_kernel(const float* __restrict__ x,
             const float* __restrict__ Wih0,
             const float* __restrict__ bih0,
             const float* __restrict__ bhh0)
{
    __shared__ float sx[64 * IN];
    const int g   = threadIdx.x;
    const int row = blockIdx.y;
    const int t0  = blockIdx.x * 64;

    const float* xs = x + ((size_t)row * SEQ + t0) * IN;
    for (int i = g; i < 64 * IN / 4; i += 256)
        ((float4*)sx)[i] = ((const float4*)xs)[i];

    u64 w[IN / 2];
    const u64* wp = (const u64*)(Wih0 + g * IN);
#pragma unroll
    for (int k = 0; k < IN / 2; k++) w[k] = wp[k];
    const u64 bp = pk(bih0[g] + bhh0[g], 0.0f);
    __syncthreads();

    for (int tt = 0; tt < 64; tt++) {
        const ulonglong2* xv = (const ulonglong2*)(sx + tt * IN);
        u64 a = bp;
#pragma unroll
        for (int k = 0; k < IN / 4; k++) {
            ulonglong2 v = xv[k];
            a = fma2(w[2 * k],     v.x, a);
            a = fma2(w[2 * k + 1], v.y, a);
        }
        g_xproj[((size_t)(t0 + tt) * Bt + row) * GATES + g] = hsum(a);
    }
}

// ============================================================================
// Main: 128 CTAs x 512 threads. Thread (g = tid&255, half = tid>>8) holds
// half-rows (32 floats = 16 u64 each) of Whh0, Wih1, Whh1 in registers.
// Phase 1: partial gates L0(t=u) and L1(t=u-1). Phase 2: combine + activate +
// cell update + head. 2 barriers/step.
// ============================================================================
__global__ void __launch_bounds__(512, 1)
lstm2_ksplit(const float* __restrict__ h0g,
             const float* __restrict__ c0g,
             const float* __restrict__ Whh0,
             const float* __restrict__ Wih1,
             const float* __restrict__ Whh1,
             const float* __restrict__ bih1,
             const float* __restrict__ bhh1,
             const float* __restrict__ Wh,
             const float* __restrict__ bhp,
             float* __restrict__ out)
{
    __shared__ float sP[2 * 2 * GATES * 2];  // [layer][row][g][half]  8KB
    __shared__ float sXP[2 * 2 * GATES];     // [buf][row][g]          4KB
    __shared__ float sH0[2 * Hs];
    __shared__ float sH1[2 * Hs];
    __shared__ float sWh[Hs];
    __shared__ float sPr[8];                 // [parity][4]

    const int tid  = threadIdx.x;
    const int g    = tid & 255;
    const int half = tid >> 8;
    const int r0   = blockIdx.x * 2;

    // register weights: half-rows
    u64 wh0[16], wx1[16], wh1[16];
    {
        const u64* p0 = (const u64*)(Whh0 + g * Hs + half * 32);
        const u64* p1 = (const u64*)(Wih1 + g * Hs + half * 32);
        const u64* p2 = (const u64*)(Whh1 + g * Hs + half * 32);
#pragma unroll
        for (int k = 0; k < 16; k++) { wh0[k] = p0[k]; wx1[k] = p1[k]; wh1[k] = p2[k]; }
    }
    const float b1 = bih1[g] + bhh1[g];      // layer1 bias (added by half==0)
    const float bh0 = bhp[0];

    float c0r = 0.0f, c1r = 0.0f;
    if (tid < 128) {                         // layer0 state threads
        int r = tid >> 6, j = tid & 63;
        sH0[r * 64 + j] = h0g[(size_t)(r0 + r) * Hs + j];
        c0r = c0g[(size_t)(r0 + r) * Hs + j];
    }
    if (tid >= 256 && tid < 384) {           // layer1 state threads
        int ub = tid - 256, r = ub >> 6, j = ub & 63;
        sH1[r * 64 + j] = h0g[(size_t)Bt * Hs + (size_t)(r0 + r) * Hs + j];
        c1r = c0g[(size_t)Bt * Hs + (size_t)(r0 + r) * Hs + j];
    }
    if (tid < 64) sWh[tid] = Wh[tid];
    if (tid >= 384) {                        // stage xproj(t=0) into buf 0
        int pf = tid - 384;
        ((float4*)sXP)[pf] =
            *(const float4*)(g_xproj + ((size_t)0 * Bt + r0) * GATES + pf * 4);
    }
    __syncthreads();

    for (int u = 0; u <= SEQ; u++) {
        // ---------- phase 1: partial gates ----------
        float4 xpf;
        const int pf = tid - 384;
        if (pf >= 0 && u + 1 < SEQ)
            xpf = *(const float4*)(g_xproj + ((size_t)(u + 1) * Bt + r0) * GATES + pf * 4);

        {
            const ulonglong2* H0 = (const ulonglong2*)sH0;  // h0(u-1)
            const ulonglong2* H1 = (const ulonglong2*)sH1;  // h1(u-2)
            // L0 accumulators seeded with xproj (half0) — stale read at u==SEQ is discarded
            float xp0 = sXP[(u & 1) * 512 + g];
            float xp1 = sXP[(u & 1) * 512 + 256 + g];
            u64 a0 = (half == 0) ? pk(xp0, 0.0f) : 0ULL;
            u64 a1 = (half == 0) ? pk(xp1, 0.0f) : 0ULL;
            u64 q0 = (half == 0) ? pk(b1, 0.0f) : 0ULL;
            u64 q1 = q0;
#pragma unroll
            for (int k = 0; k < 8; k++) {    // shared h0 loads feed Whh0 AND Wih1
                ulonglong2 v0 = H0[half * 8 + k];
                ulonglong2 v1 = H0[16 + half * 8 + k];
                a0 = fma2(wh0[2*k],   v0.x, a0);
                a0 = fma2(wh0[2*k+1], v0.y, a0);
                a1 = fma2(wh0[2*k],   v1.x, a1);
                a1 = fma2(wh0[2*k+1], v1.y, a1);
                q0 = fma2(wx1[2*k],   v0.x, q0);
                q0 = fma2(wx1[2*k+1], v0.y, q0);
                q1 = fma2(wx1[2*k],   v1.x, q1);
                q1 = fma2(wx1[2*k+1], v1.y, q1);
            }
#pragma unroll
            for (int k = 0; k < 8; k++) {    // Whh1 over h1(u-2)
                ulonglong2 v0 = H1[half * 8 + k];
                ulonglong2 v1 = H1[16 + half * 8 + k];
                q0 = fma2(wh1[2*k],   v0.x, q0);
                q0 = fma2(wh1[2*k+1], v0.y, q0);
                q1 = fma2(wh1[2*k],   v1.x, q1);
                q1 = fma2(wh1[2*k+1], v1.y, q1);
            }
            if (u < SEQ) {
                sP[(0 * 2 + 0) * 512 + g * 2 + half] = hsum(a0);
                sP[(0 * 2 + 1) * 512 + g * 2 + half] = hsum(a1);
            }
            if (u >= 1) {
                sP[(2 + 0) * 512 + g * 2 + half] = hsum(q0);
                sP[(2 + 1) * 512 + g * 2 + half] = hsum(q1);
            }
        }
        __syncthreads();

        // ---------- phase 2: combine + activate + update ----------
        if (tid < 128 && u < SEQ) {          // layer0 state, time u
            int r = tid >> 6, j = tid & 63;
            const float2* p = (const float2*)(sP + (0 * 2 + r) * 512);
            float2 vi = p[j], vf = p[64 + j], vg = p[128 + j], vo = p[192 + j];
            float gi = sigf(vi.x + vi.y);
            float gf = sigf(vf.x + vf.y);
            float gg = tanhfa(vg.x + vg.y);
            float go = sigf(vo.x + vo.y);
            c0r = gf * c0r + gi * gg;
            sH0[r * 64 + j] = go * tanhfa(c0r);
        }
        if (tid >= 256 && tid < 384 && u >= 1) {  // layer1 state, time u-1
            int ub = tid - 256, r = ub >> 6, j = ub & 63;
            const float2* p = (const float2*)(sP + (2 + r) * 512);
            float2 vi = p[j], vf = p[64 + j], vg = p[128 + j], vo = p[192 + j];
            float gi = sigf(vi.x + vi.y);
            float gf = sigf(vf.x + vf.y);
            float gg = tanhfa(vg.x + vg.y);
            float go = sigf(vo.x + vo.y);
            c1r = gf * c1r + gi * gg;
            float hn = go * tanhfa(c1r);
            sH1[r * 64 + j] = hn;
            float pr = hn * sWh[j];
#pragma unroll
            for (int off = 16; off; off >>= 1)
                pr += __shfl_down_sync(0xffffffffu, pr, off);
            if ((ub & 31) == 0) sPr[(u & 1) * 4 + (ub >> 5)] = pr;
        }
        if (pf >= 0) {
            if (u + 1 < SEQ)                 // stage xproj(u+1)
                ((float4*)sXP)[((u + 1) & 1) * 128 + pf] = xpf;
            if (u >= 2 && pf < 2) {          // head output for time u-2
                float v = sPr[((u - 1) & 1) * 4 + pf * 2]
                        + sPr[((u - 1) & 1) * 4 + pf * 2 + 1] + bh0;
                out[(size_t)(r0 + pf) * SEQ + (u - 2)] = sigf(v);
            }
        }
        __syncthreads();
    }

    // final head output for time SEQ-1 (partials written at u=SEQ, parity SEQ&1)
    if (tid >= 384 && tid < 386) {
        int k = tid - 384;
        float v = sPr[(SEQ & 1) * 4 + k * 2] + sPr[(SEQ & 1) * 4 + k * 2 + 1] + bh0;
        out[(size_t)(r0 + k) * SEQ + (SEQ - 1)] = sigf(v);
    }

    // final h, c
    const size_t hb = (size_t)Bt * SEQ;
    const size_t cb = hb + 2 * (size_t)Bt * Hs;
    if (tid < 128) {
        int r = tid >> 6, j = tid & 63;
        out[hb + (size_t)(r0 + r) * Hs + j] = sH0[r * 64 + j];
        out[cb + (size_t)(r0 + r) * Hs + j] = c0r;
    }
    if (tid >= 256 && tid < 384) {
        int ub = tid - 256, r = ub >> 6, j = ub & 63;
        out[hb + Bt * Hs + (size_t)(r0 + r) * Hs + j] = sH1[r * 64 + j];
        out[cb + Bt * Hs + (size_t)(r0 + r) * Hs + j] = c1r;
    }
}

extern "C" void kernel_launch(void* const* d_in, const int* in_sizes, int n_in,
                              void* d_out, int out_size)
{
    const float* x    = (const float*)d_in[0];
    const float* h0   = (const float*)d_in[1];
    const float* c0   = (const float*)d_in[2];
    const float* Wih0 = (const float*)d_in[3];
    const float* Whh0 = (const float*)d_in[4];
    const float* bih0 = (const float*)d_in[5];
    const float* bhh0 = (const float*)d_in[6];
    const float* Wih1 = (const float*)d_in[7];
    const float* Whh1 = (const float*)d_in[8];
    const float* bih1 = (const float*)d_in[9];
    const float* bhh1 = (const float*)d_in[10];
    const float* Wh   = (const float*)d_in[11];
    const float* bh   = (const float*)d_in[12];
    float* out = (float*)d_out;

    dim3 pre_grid(SEQ / 64, Bt);
    xproj_kernel<<<pre_grid, 256>>>(x, Wih0, bih0, bhh0);
    lstm2_ksplit<<<Bt / 2, 512>>>(h0, c0, Whh0, Wih1, Whh1,
                                  bih1, bhh1, Wh, bh, out);
}